// round 1
// baseline (speedup 1.0000x reference)
#include <cuda_runtime.h>
#include <math.h>

#define T_   512
#define B_   64
#define I_   256
#define H_   512
#define G4_  2048
#define O_   256
#define BH_  (B_*H_)
#define GREC 128

// Scratch: __device__ globals (no allocations allowed anywhere).
static __device__ float    g_pre[(size_t)T_*B_*G4_];     // 256 MB: gate pre-activations
static __device__ float    g_hsext[(size_t)(T_+1)*BH_];  // 64 MB:  h_0..h_T for current layer
static __device__ unsigned g_bar;                        // grid barrier counter

__device__ __forceinline__ float sigf(float x){ return 1.0f/(1.0f+expf(-x)); }

__global__ void reset_bar_k(){ g_bar = 0u; }

// ---------------------------------------------------------------------------
// C[m,n] = A[m,K] * W[n,K]^T + b1[n] + b2[n]   ->  g_pre
// Block tile 64x64, 256 threads, 4x4 per-thread register tile, K-tile 16.
// ---------------------------------------------------------------------------
template<int K, bool FROM_HS>
__global__ void __launch_bounds__(256)
gemm_bias_k(const float* __restrict__ Aext, const float* __restrict__ Wm,
            const float* __restrict__ b1,   const float* __restrict__ b2)
{
    const float* A = FROM_HS ? (const float*)(g_hsext + BH_) : Aext;
    __shared__ float As[16][68];
    __shared__ float Bs[16][68];
    const int tid = threadIdx.x;
    const int n0  = blockIdx.x * 64;
    const int m0  = blockIdx.y * 64;
    const int lr  = tid >> 2;          // 0..63 row within tile
    const int lk  = (tid & 3) << 2;    // 0,4,8,12
    const int rm  = (tid & 15) << 2;
    const int rn  = (tid >> 4) << 2;

    float acc[4][4];
    #pragma unroll
    for (int i=0;i<4;i++)
        #pragma unroll
        for (int j=0;j<4;j++) acc[i][j] = 0.f;

    for (int k0 = 0; k0 < K; k0 += 16) {
        float4 av = *reinterpret_cast<const float4*>(A  + (size_t)(m0+lr)*K + k0 + lk);
        float4 bv = *reinterpret_cast<const float4*>(Wm + (size_t)(n0+lr)*K + k0 + lk);
        As[lk+0][lr]=av.x; As[lk+1][lr]=av.y; As[lk+2][lr]=av.z; As[lk+3][lr]=av.w;
        Bs[lk+0][lr]=bv.x; Bs[lk+1][lr]=bv.y; Bs[lk+2][lr]=bv.z; Bs[lk+3][lr]=bv.w;
        __syncthreads();
        #pragma unroll
        for (int k=0;k<16;k++){
            float am[4], bn[4];
            #pragma unroll
            for (int i=0;i<4;i++){ am[i]=As[k][rm+i]; bn[i]=Bs[k][rn+i]; }
            #pragma unroll
            for (int i=0;i<4;i++)
                #pragma unroll
                for (int j=0;j<4;j++)
                    acc[i][j] = fmaf(am[i], bn[j], acc[i][j]);
        }
        __syncthreads();
    }
    #pragma unroll
    for (int i=0;i<4;i++){
        #pragma unroll
        for (int j=0;j<4;j++){
            int n = n0 + rn + j;
            g_pre[(size_t)(m0+rm+i)*G4_ + n] = acc[i][j] + b1[n] + b2[n];
        }
    }
}

// ---------------------------------------------------------------------------
// Grid-wide barrier: monotonic counter, all 128 CTAs co-resident (128 <= 148
// SMs, 256 thr, ~6 KB smem -> wave 1 guaranteed in practice).
// ---------------------------------------------------------------------------
__device__ __forceinline__ void grid_bar(unsigned target){
    __syncthreads();                      // all CTA writes done program-order
    if (threadIdx.x == 0){
        __threadfence();                  // release
        atomicAdd(&g_bar, 1u);
        volatile unsigned* p = &g_bar;
        while (*p < target) { }
        __threadfence();                  // acquire
    }
    __syncthreads();
}

// ---------------------------------------------------------------------------
// Persistent recurrence. 128 CTAs = 32 n-groups x 4 b-groups; each CTA owns
// ALL FOUR gates of a (16n x 16b) tile -> c stays in smem for all 512 steps.
// Per step: gates = pre[t] + h_{t} @ W_hh^T (thread tile 2b x 2j, k-vec 4),
// then fused elementwise update, h_{t+1} -> g_hsext, grid barrier.
// ---------------------------------------------------------------------------
__global__ void __launch_bounds__(256, 1)
lstm_rec_k(const float* __restrict__ Whh, const float* __restrict__ h0,
           const float* __restrict__ c0)
{
    __shared__ float gs[16][65];   // [b_local][j_local] gate staging
    __shared__ float c_sm[256];    // cell state, persistent across steps
    const int tid   = threadIdx.x;
    const int cta   = blockIdx.x;
    const int nbase = (cta & 31) << 4;   // 32 n-groups * 16
    const int bbase = (cta >> 5) << 4;   // 4  b-groups * 16

    const int bl = tid & 15, nl = tid >> 4;
    {   // install h0 slice into hsext[0]; c0 into smem
        size_t idx = (size_t)(bbase + bl)*H_ + (nbase + nl);
        g_hsext[idx] = h0[idx];
        c_sm[tid]    = c0[idx];
    }

    // GEMM thread coords: tx -> batch pair, ty -> row pair (64 rows = 4g x 16n)
    const int tx  = tid & 7;
    const int ty  = tid >> 3;
    const int jl0 = ty << 1, jl1 = jl0 + 1;
    const int r0  = (jl0 >> 4)*H_ + nbase + (jl0 & 15);  // W_hh row index
    const int r1  = (jl1 >> 4)*H_ + nbase + (jl1 & 15);
    const float* w0 = Whh + (size_t)r0 * H_;
    const float* w1 = Whh + (size_t)r1 * H_;
    const int b0  = bbase + (tx << 1);

    grid_bar(GREC);   // h0 visible everywhere

    for (int t = 0; t < T_; ++t){
        const float* hb0 = g_hsext + (size_t)t*BH_ + (size_t)b0*H_;
        const float* hb1 = hb0 + H_;
        float a00=0.f, a01=0.f, a10=0.f, a11=0.f;
        #pragma unroll 2
        for (int k = 0; k < H_; k += 4){
            float4 h0v = *reinterpret_cast<const float4*>(hb0 + k);
            float4 h1v = *reinterpret_cast<const float4*>(hb1 + k);
            float4 w0v = *reinterpret_cast<const float4*>(w0  + k);
            float4 w1v = *reinterpret_cast<const float4*>(w1  + k);
            a00 = fmaf(h0v.x, w0v.x, a00); a00 = fmaf(h0v.y, w0v.y, a00);
            a00 = fmaf(h0v.z, w0v.z, a00); a00 = fmaf(h0v.w, w0v.w, a00);
            a01 = fmaf(h0v.x, w1v.x, a01); a01 = fmaf(h0v.y, w1v.y, a01);
            a01 = fmaf(h0v.z, w1v.z, a01); a01 = fmaf(h0v.w, w1v.w, a01);
            a10 = fmaf(h1v.x, w0v.x, a10); a10 = fmaf(h1v.y, w0v.y, a10);
            a10 = fmaf(h1v.z, w0v.z, a10); a10 = fmaf(h1v.w, w0v.w, a10);
            a11 = fmaf(h1v.x, w1v.x, a11); a11 = fmaf(h1v.y, w1v.y, a11);
            a11 = fmaf(h1v.z, w1v.z, a11); a11 = fmaf(h1v.w, w1v.w, a11);
        }
        const float* pb = g_pre + ((size_t)t*B_ + b0)*G4_;
        gs[(tx<<1)  ][jl0] = a00 + pb[r0];
        gs[(tx<<1)  ][jl1] = a01 + pb[r1];
        gs[(tx<<1)+1][jl0] = a10 + pb[G4_ + r0];
        gs[(tx<<1)+1][jl1] = a11 + pb[G4_ + r1];
        __syncthreads();
        {   // fused elementwise: PyTorch gate order i,f,g,o
            float ii = sigf (gs[bl][     nl]);
            float ff = sigf (gs[bl][16 + nl]);
            float gg = tanhf(gs[bl][32 + nl]);
            float oo = sigf (gs[bl][48 + nl]);
            float c  = ff * c_sm[tid] + ii * gg;
            c_sm[tid] = c;
            float h  = oo * tanhf(c);
            g_hsext[(size_t)(t+1)*BH_ + (size_t)(bbase+bl)*H_ + (nbase+nl)] = h;
        }
        grid_bar((unsigned)(t + 2) * GREC);
    }
}

// ---------------------------------------------------------------------------
// out[b,o] = h_T[b,:] . W_out[o,:] + b_out[o]
// ---------------------------------------------------------------------------
__global__ void __launch_bounds__(256)
out_head_k(const float* __restrict__ Wo, const float* __restrict__ bo,
           float* __restrict__ out)
{
    __shared__ float hs[H_];
    const int b = blockIdx.x;
    const float* hl = g_hsext + (size_t)T_*BH_ + (size_t)b*H_;
    for (int k = threadIdx.x; k < H_; k += blockDim.x) hs[k] = hl[k];
    __syncthreads();
    const int o = threadIdx.x;          // 256 threads == O_
    const float* wr = Wo + (size_t)o * H_;
    float acc = 0.f;
    #pragma unroll 4
    for (int k = 0; k < H_; k += 4){
        float4 w = *reinterpret_cast<const float4*>(wr + k);
        acc = fmaf(hs[k  ], w.x, acc);
        acc = fmaf(hs[k+1], w.y, acc);
        acc = fmaf(hs[k+2], w.z, acc);
        acc = fmaf(hs[k+3], w.w, acc);
    }
    out[(size_t)b*O_ + o] = acc + bo[o];
}

// ---------------------------------------------------------------------------
extern "C" void kernel_launch(void* const* d_in, const int* in_sizes, int n_in,
                              void* d_out, int out_size)
{
    const float* x     = (const float*)d_in[0];
    const float* hc    = (const float*)d_in[1];   // [2, L, B, H]
    const float* W_ih0 = (const float*)d_in[2];
    const float* W_hh0 = (const float*)d_in[3];
    const float* b_ih0 = (const float*)d_in[4];
    const float* b_hh0 = (const float*)d_in[5];
    const float* W_ih1 = (const float*)d_in[6];
    const float* W_hh1 = (const float*)d_in[7];
    const float* b_ih1 = (const float*)d_in[8];
    const float* b_hh1 = (const float*)d_in[9];
    const float* W_out = (const float*)d_in[10];
    const float* b_out = (const float*)d_in[11];
    float* out = (float*)d_out;

    const float* h0_l0 = hc;              // [0,0]
    const float* h0_l1 = hc + BH_;        // [0,1]
    const float* c0_l0 = hc + 2*BH_;      // [1,0]
    const float* c0_l1 = hc + 3*BH_;      // [1,1]

    dim3 ggrid(G4_/64, (T_*B_)/64);       // (32, 512)

    // Layer 0
    gemm_bias_k<I_, false><<<ggrid, 256>>>(x, W_ih0, b_ih0, b_hh0);
    reset_bar_k<<<1,1>>>();
    lstm_rec_k<<<GREC, 256>>>(W_hh0, h0_l0, c0_l0);

    // Layer 1 (reads hs0 = g_hsext+BH_ internally)
    gemm_bias_k<H_, true><<<ggrid, 256>>>(nullptr, W_ih1, b_ih1, b_hh1);
    reset_bar_k<<<1,1>>>();
    lstm_rec_k<<<GREC, 256>>>(W_hh1, h0_l1, c0_l1);

    // Output head on h_T of layer 1
    out_head_k<<<B_, 256>>>(W_out, b_out, out);
}

// round 2
// speedup vs baseline: 2.7020x; 2.7020x over previous
#include <cuda_runtime.h>
#include <math.h>

#define T_   512
#define B_   64
#define I_   256
#define H_   512
#define G4_  2048
#define O_   256
#define BH_  (B_*H_)
#define GREC 128
#define KC   32

// Scratch: __device__ globals (no allocations allowed anywhere).
static __device__ float    g_pre[(size_t)T_*B_*G4_];     // 256 MB: gate pre-activations
static __device__ float    g_hsext[(size_t)(T_+1)*BH_];  // 64 MB:  h_0..h_T for current layer
static __device__ unsigned g_bar;                        // grid barrier counter

__device__ __forceinline__ float sigf(float x){ return 1.0f/(1.0f+expf(-x)); }

__global__ void reset_bar_k(){ g_bar = 0u; }

// ---------------------------------------------------------------------------
// C[m,n] = A[m,K] * W[n,K]^T + b1[n] + b2[n]   ->  g_pre
// Block tile 64x64, 256 threads, 4x4 per-thread register tile, K-tile 16.
// Smem stride 72 -> 16B-aligned rows -> float4 LDS (FMA-bound inner loop).
// ---------------------------------------------------------------------------
template<int K, bool FROM_HS>
__global__ void __launch_bounds__(256)
gemm_bias_k(const float* __restrict__ Aext, const float* __restrict__ Wm,
            const float* __restrict__ b1,   const float* __restrict__ b2)
{
    const float* A = FROM_HS ? (const float*)(g_hsext + BH_) : Aext;
    __shared__ float As[16][72];
    __shared__ float Bs[16][72];
    const int tid = threadIdx.x;
    const int n0  = blockIdx.x * 64;
    const int m0  = blockIdx.y * 64;
    const int lr  = tid >> 2;          // 0..63 row within tile
    const int lk  = (tid & 3) << 2;    // 0,4,8,12
    const int rm  = (tid & 15) << 2;
    const int rn  = (tid >> 4) << 2;

    float acc[4][4];
    #pragma unroll
    for (int i=0;i<4;i++)
        #pragma unroll
        for (int j=0;j<4;j++) acc[i][j] = 0.f;

    for (int k0 = 0; k0 < K; k0 += 16) {
        float4 av = *reinterpret_cast<const float4*>(A  + (size_t)(m0+lr)*K + k0 + lk);
        float4 bv = *reinterpret_cast<const float4*>(Wm + (size_t)(n0+lr)*K + k0 + lk);
        As[lk+0][lr]=av.x; As[lk+1][lr]=av.y; As[lk+2][lr]=av.z; As[lk+3][lr]=av.w;
        Bs[lk+0][lr]=bv.x; Bs[lk+1][lr]=bv.y; Bs[lk+2][lr]=bv.z; Bs[lk+3][lr]=bv.w;
        __syncthreads();
        #pragma unroll
        for (int k=0;k<16;k++){
            float4 am = *reinterpret_cast<const float4*>(&As[k][rm]);
            float4 bn = *reinterpret_cast<const float4*>(&Bs[k][rn]);
            float a[4] = {am.x, am.y, am.z, am.w};
            float b[4] = {bn.x, bn.y, bn.z, bn.w};
            #pragma unroll
            for (int i=0;i<4;i++)
                #pragma unroll
                for (int j=0;j<4;j++)
                    acc[i][j] = fmaf(a[i], b[j], acc[i][j]);
        }
        __syncthreads();
    }
    #pragma unroll
    for (int i=0;i<4;i++){
        #pragma unroll
        for (int j=0;j<4;j++){
            int n = n0 + rn + j;
            g_pre[(size_t)(m0+rm+i)*G4_ + n] = acc[i][j] + b1[n] + b2[n];
        }
    }
}

// ---------------------------------------------------------------------------
// Grid-wide barrier: monotonic counter, all 128 CTAs co-resident.
// ---------------------------------------------------------------------------
__device__ __forceinline__ void grid_bar(unsigned target){
    __syncthreads();
    if (threadIdx.x == 0){
        __threadfence();                  // release
        atomicAdd(&g_bar, 1u);
        volatile unsigned* p = &g_bar;
        while (*p < target) { }
        __threadfence();                  // acquire
    }
    __syncthreads();
}

// ---------------------------------------------------------------------------
// Persistent recurrence. 128 CTAs = 32 n-groups x 4 b-groups; each CTA owns
// ALL FOUR gates of a (16b x 16n) tile. Per step the CTA computes
// C[16b x 64rows] = h[16b x 512] @ Whh_rows[64 x 512]^T via a double-buffered
// shared-memory GEMM (Kc=32 chunks), then fused elementwise + h store + grid
// barrier. Cell state c lives in smem for all 512 steps.
// ---------------------------------------------------------------------------
__global__ void __launch_bounds__(256, 1)
lstm_rec_k(const float* __restrict__ Whh, const float* __restrict__ h0,
           const float* __restrict__ c0)
{
    __shared__ float hA[2][16][KC+4];   // stride 36 words: conflict-free, 16B-aligned
    __shared__ float wA[2][64][KC+4];
    __shared__ float gs[16][68];        // [b_local][gate*16 + n_local]
    __shared__ float c_sm[256];
    const int tid   = threadIdx.x;
    const int cta   = blockIdx.x;
    const int nbase = (cta & 31) << 4;   // 32 n-groups * 16
    const int bbase = (cta >> 5) << 4;   // 4  b-groups * 16

    // elementwise mapping: coalesced h stores (nl contiguous within warp)
    const int bl = tid >> 4, nl = tid & 15;
    {   // install h0 slice into hsext[0]; c0 into smem
        size_t idx = (size_t)(bbase + bl)*H_ + (nbase + nl);
        g_hsext[idx] = h0[idx];
        c_sm[tid]    = c0[idx];
    }

    // GEMM mapping: thread -> (b rows tx, tx+8) x (W local rows 2ty, 2ty+1)
    const int tx = tid & 7;
    const int ty = tid >> 3;            // 0..31
    const int r0 = ty << 1, r1 = r0 + 1;

    // W chunk staging: 512 float4/chunk, 2 per thread
    const float* wsrc0; const float* wsrc1;
    {
        int idx = tid;                  // j = 0
        int lr = idx >> 3, kk = (idx & 7) << 2;
        int grow = (lr >> 4)*H_ + nbase + (lr & 15);
        wsrc0 = Whh + (size_t)grow*H_ + kk;
        idx = tid + 256;                // j = 1
        lr = idx >> 3; kk = (idx & 7) << 2;
        grow = (lr >> 4)*H_ + nbase + (lr & 15);
        wsrc1 = Whh + (size_t)grow*H_ + kk;
    }
    const int wl_lr0 = tid >> 3,         wl_kk0 = (tid & 7) << 2;
    const int wl_lr1 = (tid + 256) >> 3, wl_kk1 = (tid & 7) << 2;
    // h chunk staging: 128 float4/chunk, tid<128 only
    const int hl_lr = tid >> 3, hl_kk = (tid & 7) << 2;

    grid_bar(GREC);   // h0 visible everywhere

    for (int t = 0; t < T_; ++t){
        // prefetch pre-activations for this thread's (bl, nl) -> latency hidden
        const float* pb = g_pre + ((size_t)t*B_ + bbase + bl)*G4_ + nbase + nl;
        const float p_i = pb[0], p_f = pb[512], p_g = pb[1024], p_o = pb[1536];

        const float* hstep = g_hsext + (size_t)t*BH_ + (size_t)bbase*H_;

        // preload chunk 0 -> buf 0
        {
            float4 w0 = *reinterpret_cast<const float4*>(wsrc0);
            float4 w1 = *reinterpret_cast<const float4*>(wsrc1);
            *reinterpret_cast<float4*>(&wA[0][wl_lr0][wl_kk0]) = w0;
            *reinterpret_cast<float4*>(&wA[0][wl_lr1][wl_kk1]) = w1;
            if (tid < 128){
                float4 hv = *reinterpret_cast<const float4*>(hstep + (size_t)hl_lr*H_ + hl_kk);
                *reinterpret_cast<float4*>(&hA[0][hl_lr][hl_kk]) = hv;
            }
        }
        __syncthreads();

        float a00=0.f, a01=0.f, a10=0.f, a11=0.f;
        #pragma unroll 1
        for (int c = 0; c < H_/KC; ++c){
            const int cb = c & 1;
            if (c < H_/KC - 1){
                const int nb = cb ^ 1;
                const int k0 = (c + 1) * KC;
                float4 w0 = *reinterpret_cast<const float4*>(wsrc0 + k0);
                float4 w1 = *reinterpret_cast<const float4*>(wsrc1 + k0);
                *reinterpret_cast<float4*>(&wA[nb][wl_lr0][wl_kk0]) = w0;
                *reinterpret_cast<float4*>(&wA[nb][wl_lr1][wl_kk1]) = w1;
                if (tid < 128){
                    float4 hv = *reinterpret_cast<const float4*>(hstep + (size_t)hl_lr*H_ + k0 + hl_kk);
                    *reinterpret_cast<float4*>(&hA[nb][hl_lr][hl_kk]) = hv;
                }
            }
            #pragma unroll
            for (int kk = 0; kk < KC; kk += 4){
                float4 ha = *reinterpret_cast<const float4*>(&hA[cb][tx    ][kk]);
                float4 hc = *reinterpret_cast<const float4*>(&hA[cb][tx + 8][kk]);
                float4 wa = *reinterpret_cast<const float4*>(&wA[cb][r0][kk]);
                float4 wb = *reinterpret_cast<const float4*>(&wA[cb][r1][kk]);
                a00 = fmaf(ha.x, wa.x, a00); a00 = fmaf(ha.y, wa.y, a00);
                a00 = fmaf(ha.z, wa.z, a00); a00 = fmaf(ha.w, wa.w, a00);
                a01 = fmaf(ha.x, wb.x, a01); a01 = fmaf(ha.y, wb.y, a01);
                a01 = fmaf(ha.z, wb.z, a01); a01 = fmaf(ha.w, wb.w, a01);
                a10 = fmaf(hc.x, wa.x, a10); a10 = fmaf(hc.y, wa.y, a10);
                a10 = fmaf(hc.z, wa.z, a10); a10 = fmaf(hc.w, wa.w, a10);
                a11 = fmaf(hc.x, wb.x, a11); a11 = fmaf(hc.y, wb.y, a11);
                a11 = fmaf(hc.z, wb.z, a11); a11 = fmaf(hc.w, wb.w, a11);
            }
            __syncthreads();
        }

        // stage gates
        gs[tx    ][r0] = a00;
        gs[tx    ][r1] = a01;
        gs[tx + 8][r0] = a10;
        gs[tx + 8][r1] = a11;
        __syncthreads();

        {   // fused elementwise: PyTorch gate order i,f,g,o
            float ii = sigf (gs[bl][     nl] + p_i);
            float ff = sigf (gs[bl][16 + nl] + p_f);
            float gg = tanhf(gs[bl][32 + nl] + p_g);
            float oo = sigf (gs[bl][48 + nl] + p_o);
            float c  = ff * c_sm[tid] + ii * gg;
            c_sm[tid] = c;
            float h  = oo * tanhf(c);
            g_hsext[(size_t)(t+1)*BH_ + (size_t)(bbase+bl)*H_ + (nbase+nl)] = h;
        }
        grid_bar((unsigned)(t + 2) * GREC);
    }
}

// ---------------------------------------------------------------------------
// out[b,o] = h_T[b,:] . W_out[o,:] + b_out[o]
// ---------------------------------------------------------------------------
__global__ void __launch_bounds__(256)
out_head_k(const float* __restrict__ Wo, const float* __restrict__ bo,
           float* __restrict__ out)
{
    __shared__ float hs[H_];
    const int b = blockIdx.x;
    const float* hl = g_hsext + (size_t)T_*BH_ + (size_t)b*H_;
    for (int k = threadIdx.x; k < H_; k += blockDim.x) hs[k] = hl[k];
    __syncthreads();
    const int o = threadIdx.x;          // 256 threads == O_
    const float* wr = Wo + (size_t)o * H_;
    float acc = 0.f;
    #pragma unroll 4
    for (int k = 0; k < H_; k += 4){
        float4 w = *reinterpret_cast<const float4*>(wr + k);
        acc = fmaf(hs[k  ], w.x, acc);
        acc = fmaf(hs[k+1], w.y, acc);
        acc = fmaf(hs[k+2], w.z, acc);
        acc = fmaf(hs[k+3], w.w, acc);
    }
    out[(size_t)b*O_ + o] = acc + bo[o];
}

// ---------------------------------------------------------------------------
extern "C" void kernel_launch(void* const* d_in, const int* in_sizes, int n_in,
                              void* d_out, int out_size)
{
    const float* x     = (const float*)d_in[0];
    const float* hc    = (const float*)d_in[1];   // [2, L, B, H]
    const float* W_ih0 = (const float*)d_in[2];
    const float* W_hh0 = (const float*)d_in[3];
    const float* b_ih0 = (const float*)d_in[4];
    const float* b_hh0 = (const float*)d_in[5];
    const float* W_ih1 = (const float*)d_in[6];
    const float* W_hh1 = (const float*)d_in[7];
    const float* b_ih1 = (const float*)d_in[8];
    const float* b_hh1 = (const float*)d_in[9];
    const float* W_out = (const float*)d_in[10];
    const float* b_out = (const float*)d_in[11];
    float* out = (float*)d_out;

    const float* h0_l0 = hc;              // [0,0]
    const float* h0_l1 = hc + BH_;        // [0,1]
    const float* c0_l0 = hc + 2*BH_;      // [1,0]
    const float* c0_l1 = hc + 3*BH_;      // [1,1]

    dim3 ggrid(G4_/64, (T_*B_)/64);       // (32, 512)

    // Layer 0
    gemm_bias_k<I_, false><<<ggrid, 256>>>(x, W_ih0, b_ih0, b_hh0);
    reset_bar_k<<<1,1>>>();
    lstm_rec_k<<<GREC, 256>>>(W_hh0, h0_l0, c0_l0);

    // Layer 1 (reads hs0 = g_hsext+BH_ internally)
    gemm_bias_k<H_, true><<<ggrid, 256>>>(nullptr, W_ih1, b_ih1, b_hh1);
    reset_bar_k<<<1,1>>>();
    lstm_rec_k<<<GREC, 256>>>(W_hh1, h0_l1, c0_l1);

    // Output head on h_T of layer 1
    out_head_k<<<B_, 256>>>(W_out, b_out, out);
}

// round 5
// speedup vs baseline: 5.6580x; 2.0940x over previous
#include <cuda_runtime.h>
#include <cuda_fp16.h>
#include <math.h>

#define T_   512
#define B_   64
#define I_   256
#define H_   512
#define G4_  2048
#define O_   256
#define BH_  (B_*H_)
#define GREC 128

// ---------------- scratch (device globals; no allocations anywhere) --------
static __device__ float    g_pre[(size_t)T_*B_*G4_];      // 256 MB gate preacts
static __device__ float    g_hsext[(size_t)(T_+1)*BH_];   // 64 MB h_0..h_T (f32)
static __device__ __half   g_hhi[(size_t)(T_+1)*BH_];     // h hi (f16), per t
static __device__ __half   g_hlo[(size_t)(T_+1)*BH_];     // h lo (f16)
static __device__ __half   g_whhhi[(size_t)G4_*H_];       // split W_hh
static __device__ __half   g_whhlo[(size_t)G4_*H_];
static __device__ unsigned g_bar;

__device__ __forceinline__ float sigf(float x){ return 1.0f/(1.0f+expf(-x)); }

__global__ void reset_bar_k(){ g_bar = 0u; }

// f32 -> (f16 hi, f16 lo) split
__global__ void split_k(const float* __restrict__ src, __half* __restrict__ hi,
                        __half* __restrict__ lo, int n){
    int i = blockIdx.x*blockDim.x + threadIdx.x;
    if (i < n){
        float v = src[i];
        __half h = __float2half_rn(v);
        hi[i] = h;
        lo[i] = __float2half_rn(v - __half2float(h));
    }
}

// ---------------- mma helpers ----------------------------------------------
__device__ __forceinline__ unsigned smem_u32(const void* p){
    return (unsigned)__cvta_generic_to_shared(p);
}
__device__ __forceinline__ void ldsm_x4(const void* p, unsigned* r){
    asm volatile("ldmatrix.sync.aligned.m8n8.x4.shared.b16 {%0,%1,%2,%3}, [%4];"
        : "=r"(r[0]),"=r"(r[1]),"=r"(r[2]),"=r"(r[3]) : "r"(smem_u32(p)) : "memory");
}
__device__ __forceinline__ void ldsm_x2(const void* p, unsigned* r){
    asm volatile("ldmatrix.sync.aligned.m8n8.x2.shared.b16 {%0,%1}, [%2];"
        : "=r"(r[0]),"=r"(r[1]) : "r"(smem_u32(p)) : "memory");
}
__device__ __forceinline__ void mma16816(float* c, const unsigned* a, const unsigned* b){
    asm volatile("mma.sync.aligned.m16n8k16.row.col.f32.f16.f16.f32 "
        "{%0,%1,%2,%3}, {%4,%5,%6,%7}, {%8,%9}, {%0,%1,%2,%3};"
        : "+f"(c[0]),"+f"(c[1]),"+f"(c[2]),"+f"(c[3])
        : "r"(a[0]),"r"(a[1]),"r"(a[2]),"r"(a[3]),"r"(b[0]),"r"(b[1]));
}

// ---------------------------------------------------------------------------
// PROVEN R2 fp32 pre-GEMM:
// g_pre[m,n] = A[m,K] * W[n,K]^T + b1[n] + b2[n]
// ---------------------------------------------------------------------------
template<int K, bool FROM_HS>
__global__ void __launch_bounds__(256)
gemm_bias_k(const float* __restrict__ Aext, const float* __restrict__ Wm,
            const float* __restrict__ b1,   const float* __restrict__ b2)
{
    const float* A = FROM_HS ? (const float*)(g_hsext + BH_) : Aext;
    __shared__ float As[16][72];
    __shared__ float Bs[16][72];
    const int tid = threadIdx.x;
    const int n0  = blockIdx.x * 64;
    const int m0  = blockIdx.y * 64;
    const int lr  = tid >> 2;
    const int lk  = (tid & 3) << 2;
    const int rm  = (tid & 15) << 2;
    const int rn  = (tid >> 4) << 2;

    float acc[4][4];
    #pragma unroll
    for (int i=0;i<4;i++)
        #pragma unroll
        for (int j=0;j<4;j++) acc[i][j] = 0.f;

    for (int k0 = 0; k0 < K; k0 += 16) {
        float4 av = *reinterpret_cast<const float4*>(A  + (size_t)(m0+lr)*K + k0 + lk);
        float4 bv = *reinterpret_cast<const float4*>(Wm + (size_t)(n0+lr)*K + k0 + lk);
        As[lk+0][lr]=av.x; As[lk+1][lr]=av.y; As[lk+2][lr]=av.z; As[lk+3][lr]=av.w;
        Bs[lk+0][lr]=bv.x; Bs[lk+1][lr]=bv.y; Bs[lk+2][lr]=bv.z; Bs[lk+3][lr]=bv.w;
        __syncthreads();
        #pragma unroll
        for (int k=0;k<16;k++){
            float4 am = *reinterpret_cast<const float4*>(&As[k][rm]);
            float4 bn = *reinterpret_cast<const float4*>(&Bs[k][rn]);
            float a[4] = {am.x, am.y, am.z, am.w};
            float b[4] = {bn.x, bn.y, bn.z, bn.w};
            #pragma unroll
            for (int i=0;i<4;i++)
                #pragma unroll
                for (int j=0;j<4;j++)
                    acc[i][j] = fmaf(a[i], b[j], acc[i][j]);
        }
        __syncthreads();
    }
    #pragma unroll
    for (int i=0;i<4;i++){
        #pragma unroll
        for (int j=0;j<4;j++){
            int n = n0 + rn + j;
            g_pre[(size_t)(m0+rm+i)*G4_ + n] = acc[i][j] + b1[n] + b2[n];
        }
    }
}

// ---------------------------------------------------------------------------
// Grid-wide barrier: monotonic counter, 128 co-resident CTAs.
// ---------------------------------------------------------------------------
__device__ __forceinline__ void grid_bar(unsigned target){
    __syncthreads();
    if (threadIdx.x == 0){
        __threadfence();                  // release
        atomicAdd(&g_bar, 1u);
        volatile unsigned* p = &g_bar;
        while (*p < target) { }
        __threadfence();                  // acquire
    }
    __syncthreads();
}

// ---------------------------------------------------------------------------
// Persistent recurrence, HMMA split-f16 (R3 version + f32 h store).
// 128 CTAs = 32 n-groups x 4 b-groups. CTA tile: 16 batches x 64 W-rows
// (= 4 gates x 16 n). W (hi+lo) resides in smem for all 512 steps; h staged
// per step from g_hhi/g_hlo. 8 warps split K (64 k each, 4 ksteps of 16).
// Partials reduced in smem, fused elementwise, h stored f32 + f16 hi/lo.
// smem: W 133120 + h 33280 + P 34816 + c 1024 = 202240 B (dynamic).
// ---------------------------------------------------------------------------
#define SMEM_REC 202240

__global__ void __launch_bounds__(256, 1)
lstm_rec_k(const __half* __restrict__ Whh_hi, const __half* __restrict__ Whh_lo,
           const float* __restrict__ h0, const float* __restrict__ c0)
{
    extern __shared__ char smraw[];
    __half* Wh  = (__half*)smraw;            // [64][520]
    __half* Wl  = Wh + 64*520;               // [64][520]
    __half* Hh  = Wl + 64*520;               // [16][520]
    __half* Hl  = Hh + 16*520;               // [16][520]
    float*  P   = (float*)(Hl + 16*520);     // [8][16][68]
    float*  Csm = P + 8*16*68;               // [256]

    const int tid   = threadIdx.x;
    const int cta   = blockIdx.x;
    const int nbase = (cta & 31) << 4;
    const int bbase = (cta >> 5) << 4;
    const int bl = tid >> 4, nl = tid & 15;

    {   // install split h0 + c0
        size_t idx = (size_t)(bbase + bl)*H_ + (nbase + nl);
        Csm[tid] = c0[idx];
        float hv = h0[idx];
        __half hh = __float2half_rn(hv);
        g_hhi[idx] = hh;
        g_hlo[idx] = __float2half_rn(hv - __half2float(hh));
        g_hsext[idx] = hv;
    }

    // preload W tile (64 rows x 512) hi+lo into smem (rows padded to 520)
    for (int i = tid; i < 64*64; i += 256){
        int lr = i >> 6, cc = (i & 63) * 8;
        int grow = (lr >> 4)*H_ + nbase + (lr & 15);
        *(uint4*)&Wh[lr*520 + cc] = *(const uint4*)&Whh_hi[(size_t)grow*H_ + cc];
        *(uint4*)&Wl[lr*520 + cc] = *(const uint4*)&Whh_lo[(size_t)grow*H_ + cc];
    }

    const int wid = tid >> 5, lane = tid & 31;
    const int g   = lane >> 2, tig = lane & 3;
    const int a_row = lane & 15, a_co = (lane >> 4) * 8;
    const int b_row = lane & 7,  b_co = ((lane >> 3) & 1) * 8;

    grid_bar(GREC);   // h0 visible everywhere; W smem loaded

    for (int t = 0; t < T_; ++t){
        // prefetch pre-activations (latency hidden under GEMM)
        const float* pb = g_pre + ((size_t)t*B_ + bbase + bl)*G4_ + nbase + nl;
        const float p_i = pb[0], p_f = pb[512], p_g = pb[1024], p_o = pb[1536];

        // stage h_t (16 rows x 512, hi+lo)
        {
            const __half* shi = g_hhi + (size_t)t*BH_ + (size_t)bbase*H_;
            const __half* slo = g_hlo + (size_t)t*BH_ + (size_t)bbase*H_;
            #pragma unroll
            for (int j=0;j<4;j++){
                int i = tid + j*256;
                int r = i >> 6, cc = (i & 63) * 8;
                *(uint4*)&Hh[r*520 + cc] = *(const uint4*)&shi[(size_t)r*H_ + cc];
                *(uint4*)&Hl[r*520 + cc] = *(const uint4*)&slo[(size_t)r*H_ + cc];
            }
        }
        __syncthreads();

        // warp wid covers k in [wid*64, wid*64+64)
        float acc[8][4];
        #pragma unroll
        for (int j=0;j<8;j++)
            #pragma unroll
            for (int q=0;q<4;q++) acc[j][q] = 0.f;

        #pragma unroll
        for (int ks=0; ks<4; ks++){
            const int k0 = wid*64 + ks*16;
            unsigned ah[4], al2[4];
            ldsm_x4(&Hh[a_row*520 + k0 + a_co], ah);
            ldsm_x4(&Hl[a_row*520 + k0 + a_co], al2);
            #pragma unroll
            for (int j=0;j<8;j++){
                unsigned bh[2], blr[2];
                ldsm_x2(&Wh[(8*j + b_row)*520 + k0 + b_co], bh);
                ldsm_x2(&Wl[(8*j + b_row)*520 + k0 + b_co], blr);
                mma16816(acc[j], ah,  bh);
                mma16816(acc[j], ah,  blr);
                mma16816(acc[j], al2, bh);
            }
        }

        // write per-warp partials: row = batch (g / g+8), col = W local row
        {
            float* Pw = P + wid*16*68;
            #pragma unroll
            for (int j=0;j<8;j++){
                float2 v;
                v.x = acc[j][0]; v.y = acc[j][1];
                *(float2*)&Pw[g*68 + 8*j + 2*tig] = v;
                v.x = acc[j][2]; v.y = acc[j][3];
                *(float2*)&Pw[(g+8)*68 + 8*j + 2*tig] = v;
            }
        }
        __syncthreads();

        // reduce 8 partials + fused elementwise (gate order i,f,g,o)
        {
            float s_i = p_i, s_f = p_f, s_g = p_g, s_o = p_o;
            #pragma unroll
            for (int w=0;w<8;w++){
                const float* Pw = P + w*16*68 + bl*68 + nl;
                s_i += Pw[0]; s_f += Pw[16]; s_g += Pw[32]; s_o += Pw[48];
            }
            float ii = sigf(s_i), ff = sigf(s_f);
            float gg = tanhf(s_g), oo = sigf(s_o);
            float c  = ff * Csm[tid] + ii * gg;
            Csm[tid] = c;
            float h  = oo * tanhf(c);
            size_t oidx = (size_t)(t+1)*BH_ + (size_t)(bbase+bl)*H_ + (nbase+nl);
            __half hh = __float2half_rn(h);
            g_hhi[oidx] = hh;
            g_hlo[oidx] = __float2half_rn(h - __half2float(hh));
            g_hsext[oidx] = h;               // f32 for pre-GEMM L1 + out head
        }
        grid_bar((unsigned)(t + 2) * GREC);
    }
}

// ---------------------------------------------------------------------------
// out[b,o] = h_T[b,:] . W_out[o,:] + b_out[o]
// ---------------------------------------------------------------------------
__global__ void __launch_bounds__(256)
out_head_k(const float* __restrict__ Wo, const float* __restrict__ bo,
           float* __restrict__ out)
{
    __shared__ float hs[H_];
    const int b = blockIdx.x;
    const float* hl = g_hsext + (size_t)T_*BH_ + (size_t)b*H_;
    for (int k = threadIdx.x; k < H_; k += blockDim.x) hs[k] = hl[k];
    __syncthreads();
    const int o = threadIdx.x;
    const float* wr = Wo + (size_t)o * H_;
    float acc = 0.f;
    #pragma unroll 4
    for (int k = 0; k < H_; k += 4){
        float4 w = *reinterpret_cast<const float4*>(wr + k);
        acc = fmaf(hs[k  ], w.x, acc);
        acc = fmaf(hs[k+1], w.y, acc);
        acc = fmaf(hs[k+2], w.z, acc);
        acc = fmaf(hs[k+3], w.w, acc);
    }
    out[(size_t)b*O_ + o] = acc + bo[o];
}

// ---------------------------------------------------------------------------
extern "C" void kernel_launch(void* const* d_in, const int* in_sizes, int n_in,
                              void* d_out, int out_size)
{
    const float* x     = (const float*)d_in[0];
    const float* hc    = (const float*)d_in[1];
    const float* W_ih0 = (const float*)d_in[2];
    const float* W_hh0 = (const float*)d_in[3];
    const float* b_ih0 = (const float*)d_in[4];
    const float* b_hh0 = (const float*)d_in[5];
    const float* W_ih1 = (const float*)d_in[6];
    const float* W_hh1 = (const float*)d_in[7];
    const float* b_ih1 = (const float*)d_in[8];
    const float* b_hh1 = (const float*)d_in[9];
    const float* W_out = (const float*)d_in[10];
    const float* b_out = (const float*)d_in[11];
    float* out = (float*)d_out;

    const float* h0_l0 = hc;
    const float* h0_l1 = hc + BH_;
    const float* c0_l0 = hc + 2*BH_;
    const float* c0_l1 = hc + 3*BH_;

    // idempotent; host-side attribute, not an allocation
    cudaFuncSetAttribute(lstm_rec_k,
        cudaFuncAttributeMaxDynamicSharedMemorySize, SMEM_REC);

    dim3 ggrid(G4_/64, (T_*B_)/64);       // (32, 512)

    // Layer 0: fp32 pre-GEMM (proven), HMMA recurrence
    split_k<<<(G4_*H_+255)/256, 256>>>(W_hh0, g_whhhi, g_whhlo, G4_*H_);
    gemm_bias_k<I_, false><<<ggrid, 256>>>(x, W_ih0, b_ih0, b_hh0);
    reset_bar_k<<<1,1>>>();
    lstm_rec_k<<<GREC, 256, SMEM_REC>>>(g_whhhi, g_whhlo, h0_l0, c0_l0);

    // Layer 1: fp32 pre-GEMM on hs0 (g_hsext+BH_), HMMA recurrence
    split_k<<<(G4_*H_+255)/256, 256>>>(W_hh1, g_whhhi, g_whhlo, G4_*H_);
    gemm_bias_k<H_, true><<<ggrid, 256>>>(nullptr, W_ih1, b_ih1, b_hh1);
    reset_bar_k<<<1,1>>>();
    lstm_rec_k<<<GREC, 256, SMEM_REC>>>(g_whhhi, g_whhlo, h0_l1, c0_l1);

    out_head_k<<<B_, 256>>>(W_out, b_out, out);
}

// round 10
// speedup vs baseline: 6.5849x; 1.1638x over previous
#include <cuda_runtime.h>
#include <cuda_fp16.h>
#include <math.h>

#define T_   512
#define B_   64
#define I_   256
#define H_   512
#define G4_  2048
#define O_   256
#define BH_  (B_*H_)
#define GREC 128

// ---------------- scratch (device globals; no allocations anywhere) --------
static __device__ float    g_pre[(size_t)T_*B_*G4_];      // gate preacts
static __device__ float    g_hsext[(size_t)(T_+1)*BH_];   // h_0..h_T (f32)
static __device__ __half   g_hhi[(size_t)(T_+1)*BH_];     // h hi (f16)
static __device__ __half   g_hlo[(size_t)(T_+1)*BH_];     // h lo (f16)
static __device__ __half   g_whhhi[(size_t)G4_*H_];       // split W_hh
static __device__ __half   g_whhlo[(size_t)G4_*H_];
static __device__ unsigned g_bar;

__device__ __forceinline__ float sigf(float x){ return 1.0f/(1.0f+expf(-x)); }

__global__ void reset_bar_k(){ g_bar = 0u; }

// f32 -> (f16 hi, f16 lo) split  (PROVEN: feeds the working recurrence)
__global__ void split_k(const float* __restrict__ src, __half* __restrict__ hi,
                        __half* __restrict__ lo, int n){
    int i = blockIdx.x*blockDim.x + threadIdx.x;
    if (i < n){
        float v = src[i];
        __half h = __float2half_rn(v);
        hi[i] = h;
        lo[i] = __float2half_rn(v - __half2float(h));
    }
}

// ---------------- mma helpers (PROVEN in lstm_rec_k) ------------------------
__device__ __forceinline__ unsigned smem_u32(const void* p){
    return (unsigned)__cvta_generic_to_shared(p);
}
__device__ __forceinline__ void ldsm_x4(const void* p, unsigned* r){
    asm volatile("ldmatrix.sync.aligned.m8n8.x4.shared.b16 {%0,%1,%2,%3}, [%4];"
        : "=r"(r[0]),"=r"(r[1]),"=r"(r[2]),"=r"(r[3]) : "r"(smem_u32(p)) : "memory");
}
__device__ __forceinline__ void ldsm_x2(const void* p, unsigned* r){
    asm volatile("ldmatrix.sync.aligned.m8n8.x2.shared.b16 {%0,%1}, [%2];"
        : "=r"(r[0]),"=r"(r[1]) : "r"(smem_u32(p)) : "memory");
}
__device__ __forceinline__ void mma16816(float* c, const unsigned* a, const unsigned* b){
    asm volatile("mma.sync.aligned.m16n8k16.row.col.f32.f16.f16.f32 "
        "{%0,%1,%2,%3}, {%4,%5,%6,%7}, {%8,%9}, {%0,%1,%2,%3};"
        : "+f"(c[0]),"+f"(c[1]),"+f"(c[2]),"+f"(c[3])
        : "r"(a[0]),"r"(a[1]),"r"(a[2]),"r"(a[3]),"r"(b[0]),"r"(b[1]));
}

// ---------------------------------------------------------------------------
// fp32 pre-GEMM v2: g_pre[m,n] = A[m,K] . W[n,K]^T + b1[n] + b2[n]
// 128x128 CTA tile, 256 threads, 8x8 per-thread register tile, Kc=16.
// FFMA-bound by construction (4 LDS.128 : 64 FFMA per thread per k).
// A source: harness pointer (layer 0) or g_hsext+BH_ in-kernel (layer 1) —
// both are the exact R5-proven data paths.
// ---------------------------------------------------------------------------
template<int K, bool FROM_HS>
__global__ void __launch_bounds__(256)
gemm_bias_v2(const float* __restrict__ Aext, const float* __restrict__ Wm,
             const float* __restrict__ b1,   const float* __restrict__ b2)
{
    const float* A = FROM_HS ? (const float*)(g_hsext + BH_) : Aext;
    __shared__ float As[16][132];
    __shared__ float Bs[16][132];
    const int tid = threadIdx.x;
    const int n0  = blockIdx.x * 128;
    const int m0  = blockIdx.y * 128;
    const int rm  = (tid & 15) << 3;    // 0..120
    const int rn  = (tid >> 4) << 3;    // 0..120

    float acc[8][8];
    #pragma unroll
    for (int i=0;i<8;i++)
        #pragma unroll
        for (int j=0;j<8;j++) acc[i][j] = 0.f;

    for (int k0 = 0; k0 < K; k0 += 16){
        #pragma unroll
        for (int jj = 0; jj < 2; ++jj){
            int i  = tid + jj*256;
            int r  = i >> 2;            // 0..127
            int c4 = (i & 3) << 2;      // 0,4,8,12
            float4 av = *(const float4*)&A [(size_t)(m0+r)*K + k0 + c4];
            float4 bv = *(const float4*)&Wm[(size_t)(n0+r)*K + k0 + c4];
            As[c4+0][r]=av.x; As[c4+1][r]=av.y; As[c4+2][r]=av.z; As[c4+3][r]=av.w;
            Bs[c4+0][r]=bv.x; Bs[c4+1][r]=bv.y; Bs[c4+2][r]=bv.z; Bs[c4+3][r]=bv.w;
        }
        __syncthreads();
        #pragma unroll
        for (int k = 0; k < 16; ++k){
            float a[8], b[8];
            *(float4*)&a[0] = *(const float4*)&As[k][rm];
            *(float4*)&a[4] = *(const float4*)&As[k][rm+4];
            *(float4*)&b[0] = *(const float4*)&Bs[k][rn];
            *(float4*)&b[4] = *(const float4*)&Bs[k][rn+4];
            #pragma unroll
            for (int i=0;i<8;i++)
                #pragma unroll
                for (int j=0;j<8;j++)
                    acc[i][j] = fmaf(a[i], b[j], acc[i][j]);
        }
        __syncthreads();
    }

    #pragma unroll
    for (int i=0;i<8;i++){
        const size_t mrow = (size_t)(m0 + rm + i) * G4_;
        #pragma unroll
        for (int j=0;j<8;j+=4){
            int n = n0 + rn + j;
            float4 v;
            v.x = acc[i][j  ] + b1[n  ] + b2[n  ];
            v.y = acc[i][j+1] + b1[n+1] + b2[n+1];
            v.z = acc[i][j+2] + b1[n+2] + b2[n+2];
            v.w = acc[i][j+3] + b1[n+3] + b2[n+3];
            *(float4*)&g_pre[mrow + n] = v;
        }
    }
}

// ---------------------------------------------------------------------------
// Grid-wide barrier: monotonic counter, 128 co-resident CTAs.
// ---------------------------------------------------------------------------
__device__ __forceinline__ void grid_bar(unsigned target){
    __syncthreads();
    if (threadIdx.x == 0){
        __threadfence();                  // release
        atomicAdd(&g_bar, 1u);
        volatile unsigned* p = &g_bar;
        while (*p < target) { }
        __threadfence();                  // acquire
    }
    __syncthreads();
}

// ---------------------------------------------------------------------------
// Persistent recurrence, HMMA split-f16 (PROVEN R5 version, verbatim).
// ---------------------------------------------------------------------------
#define SMEM_REC 202240

__global__ void __launch_bounds__(256, 1)
lstm_rec_k(const __half* __restrict__ Whh_hi, const __half* __restrict__ Whh_lo,
           const float* __restrict__ h0, const float* __restrict__ c0)
{
    extern __shared__ char smraw[];
    __half* Wh  = (__half*)smraw;            // [64][520]
    __half* Wl  = Wh + 64*520;               // [64][520]
    __half* Hh  = Wl + 64*520;               // [16][520]
    __half* Hl  = Hh + 16*520;               // [16][520]
    float*  P   = (float*)(Hl + 16*520);     // [8][16][68]
    float*  Csm = P + 8*16*68;               // [256]

    const int tid   = threadIdx.x;
    const int cta   = blockIdx.x;
    const int nbase = (cta & 31) << 4;
    const int bbase = (cta >> 5) << 4;
    const int bl = tid >> 4, nl = tid & 15;

    {   // install split h0 + c0
        size_t idx = (size_t)(bbase + bl)*H_ + (nbase + nl);
        Csm[tid] = c0[idx];
        float hv = h0[idx];
        __half hh = __float2half_rn(hv);
        g_hhi[idx] = hh;
        g_hlo[idx] = __float2half_rn(hv - __half2float(hh));
        g_hsext[idx] = hv;
    }

    // preload W tile (64 rows x 512) hi+lo into smem (rows padded to 520)
    for (int i = tid; i < 64*64; i += 256){
        int lr = i >> 6, cc = (i & 63) * 8;
        int grow = (lr >> 4)*H_ + nbase + (lr & 15);
        *(uint4*)&Wh[lr*520 + cc] = *(const uint4*)&Whh_hi[(size_t)grow*H_ + cc];
        *(uint4*)&Wl[lr*520 + cc] = *(const uint4*)&Whh_lo[(size_t)grow*H_ + cc];
    }

    const int wid = tid >> 5, lane = tid & 31;
    const int g   = lane >> 2, tig = lane & 3;
    const int a_row = lane & 15, a_co = (lane >> 4) * 8;
    const int b_row = lane & 7,  b_co = ((lane >> 3) & 1) * 8;

    grid_bar(GREC);   // h0 visible everywhere; W smem loaded

    for (int t = 0; t < T_; ++t){
        const float* pb = g_pre + ((size_t)t*B_ + bbase + bl)*G4_ + nbase + nl;
        const float p_i = pb[0], p_f = pb[512], p_g = pb[1024], p_o = pb[1536];

        // stage h_t (16 rows x 512, hi+lo)
        {
            const __half* shi = g_hhi + (size_t)t*BH_ + (size_t)bbase*H_;
            const __half* slo = g_hlo + (size_t)t*BH_ + (size_t)bbase*H_;
            #pragma unroll
            for (int j=0;j<4;j++){
                int i = tid + j*256;
                int r = i >> 6, cc = (i & 63) * 8;
                *(uint4*)&Hh[r*520 + cc] = *(const uint4*)&shi[(size_t)r*H_ + cc];
                *(uint4*)&Hl[r*520 + cc] = *(const uint4*)&slo[(size_t)r*H_ + cc];
            }
        }
        __syncthreads();

        float acc[8][4];
        #pragma unroll
        for (int j=0;j<8;j++)
            #pragma unroll
            for (int q=0;q<4;q++) acc[j][q] = 0.f;

        #pragma unroll
        for (int ks=0; ks<4; ks++){
            const int k0 = wid*64 + ks*16;
            unsigned ah[4], al2[4];
            ldsm_x4(&Hh[a_row*520 + k0 + a_co], ah);
            ldsm_x4(&Hl[a_row*520 + k0 + a_co], al2);
            #pragma unroll
            for (int j=0;j<8;j++){
                unsigned bh[2], blr[2];
                ldsm_x2(&Wh[(8*j + b_row)*520 + k0 + b_co], bh);
                ldsm_x2(&Wl[(8*j + b_row)*520 + k0 + b_co], blr);
                mma16816(acc[j], ah,  bh);
                mma16816(acc[j], ah,  blr);
                mma16816(acc[j], al2, bh);
            }
        }

        {
            float* Pw = P + wid*16*68;
            #pragma unroll
            for (int j=0;j<8;j++){
                float2 v;
                v.x = acc[j][0]; v.y = acc[j][1];
                *(float2*)&Pw[g*68 + 8*j + 2*tig] = v;
                v.x = acc[j][2]; v.y = acc[j][3];
                *(float2*)&Pw[(g+8)*68 + 8*j + 2*tig] = v;
            }
        }
        __syncthreads();

        {
            float s_i = p_i, s_f = p_f, s_g = p_g, s_o = p_o;
            #pragma unroll
            for (int w=0;w<8;w++){
                const float* Pw = P + w*16*68 + bl*68 + nl;
                s_i += Pw[0]; s_f += Pw[16]; s_g += Pw[32]; s_o += Pw[48];
            }
            float ii = sigf(s_i), ff = sigf(s_f);
            float gg = tanhf(s_g), oo = sigf(s_o);
            float c  = ff * Csm[tid] + ii * gg;
            Csm[tid] = c;
            float h  = oo * tanhf(c);
            size_t oidx = (size_t)(t+1)*BH_ + (size_t)(bbase+bl)*H_ + (nbase+nl);
            __half hh = __float2half_rn(h);
            g_hhi[oidx] = hh;
            g_hlo[oidx] = __float2half_rn(h - __half2float(hh));
            g_hsext[oidx] = h;
        }
        grid_bar((unsigned)(t + 2) * GREC);
    }
}

// ---------------------------------------------------------------------------
// out[b,o] = h_T[b,:] . W_out[o,:] + b_out[o]
// ---------------------------------------------------------------------------
__global__ void __launch_bounds__(256)
out_head_k(const float* __restrict__ Wo, const float* __restrict__ bo,
           float* __restrict__ out)
{
    __shared__ float hs[H_];
    const int b = blockIdx.x;
    const float* hl = g_hsext + (size_t)T_*BH_ + (size_t)b*H_;
    for (int k = threadIdx.x; k < H_; k += blockDim.x) hs[k] = hl[k];
    __syncthreads();
    const int o = threadIdx.x;
    const float* wr = Wo + (size_t)o * H_;
    float acc = 0.f;
    #pragma unroll 4
    for (int k = 0; k < H_; k += 4){
        float4 w = *reinterpret_cast<const float4*>(wr + k);
        acc = fmaf(hs[k  ], w.x, acc);
        acc = fmaf(hs[k+1], w.y, acc);
        acc = fmaf(hs[k+2], w.z, acc);
        acc = fmaf(hs[k+3], w.w, acc);
    }
    out[(size_t)b*O_ + o] = acc + bo[o];
}

// ---------------------------------------------------------------------------
extern "C" void kernel_launch(void* const* d_in, const int* in_sizes, int n_in,
                              void* d_out, int out_size)
{
    const float* x     = (const float*)d_in[0];
    const float* hc    = (const float*)d_in[1];
    const float* W_ih0 = (const float*)d_in[2];
    const float* W_hh0 = (const float*)d_in[3];
    const float* b_ih0 = (const float*)d_in[4];
    const float* b_hh0 = (const float*)d_in[5];
    const float* W_ih1 = (const float*)d_in[6];
    const float* W_hh1 = (const float*)d_in[7];
    const float* b_ih1 = (const float*)d_in[8];
    const float* b_hh1 = (const float*)d_in[9];
    const float* W_out = (const float*)d_in[10];
    const float* b_out = (const float*)d_in[11];
    float* out = (float*)d_out;

    const float* h0_l0 = hc;
    const float* h0_l1 = hc + BH_;
    const float* c0_l0 = hc + 2*BH_;
    const float* c0_l1 = hc + 3*BH_;

    // host-side attribute (idempotent, no allocation)
    cudaFuncSetAttribute(lstm_rec_k,
        cudaFuncAttributeMaxDynamicSharedMemorySize, SMEM_REC);

    dim3 pgrid(G4_/128, (T_*B_)/128);     // (16, 256)

    // Layer 0: fp32 v2 pre-GEMM (A = harness x), HMMA recurrence
    split_k<<<(G4_*H_+255)/256, 256>>>(W_hh0, g_whhhi, g_whhlo, G4_*H_);
    gemm_bias_v2<I_, false><<<pgrid, 256>>>(x, W_ih0, b_ih0, b_hh0);
    reset_bar_k<<<1,1>>>();
    lstm_rec_k<<<GREC, 256, SMEM_REC>>>(g_whhhi, g_whhlo, h0_l0, c0_l0);

    // Layer 1: fp32 v2 pre-GEMM (A = g_hsext+BH_ in-kernel), HMMA recurrence
    split_k<<<(G4_*H_+255)/256, 256>>>(W_hh1, g_whhhi, g_whhlo, G4_*H_);
    gemm_bias_v2<H_, true><<<pgrid, 256>>>(nullptr, W_ih1, b_ih1, b_hh1);
    reset_bar_k<<<1,1>>>();
    lstm_rec_k<<<GREC, 256, SMEM_REC>>>(g_whhhi, g_whhlo, h0_l1, c0_l1);

    out_head_k<<<B_, 256>>>(W_out, b_out, out);
}